// round 2
// baseline (speedup 1.0000x reference)
#include <cuda_runtime.h>
#include <cstdint>

#define B_  8
#define P_  196
#define L_  80
#define D1_ 2048
#define D2_ 300
#define A_  1024

// Scratch (device globals: allocation-free contract)
__device__ float g_p1[(size_t)B_ * P_ * A_];   // 1568 x 1024
__device__ float g_p2[(size_t)B_ * L_ * A_];   // 640 x 1024
__device__ float g_v[A_];
__device__ float g_c0[1];

// ---------------------------------------------------------------------------
// prep: v[a] = sum_c wt[c]*Wh[c][a];  c0 = wt.bh + bt
// ---------------------------------------------------------------------------
__global__ void prep_v_kernel(const float* __restrict__ Wh, const float* __restrict__ wt,
                              const float* __restrict__ bh, const float* __restrict__ bt) {
    __shared__ float red[256];
    int tid = threadIdx.x;
    int a_local = tid & 31;
    int cg = tid >> 5;                       // 0..7
    int a = blockIdx.x * 32 + a_local;
    float s = 0.f;
    int cbeg = cg * 128;
    #pragma unroll 8
    for (int c = cbeg; c < cbeg + 128; c++)
        s += wt[c] * Wh[(size_t)c * A_ + a];
    red[tid] = s;
    __syncthreads();
    if (cg == 0) {
        float t = 0.f;
        #pragma unroll
        for (int g = 0; g < 8; g++) t += red[g * 32 + a_local];
        g_v[a] = t;
    }
    __syncthreads();
    if (blockIdx.x == 0) {
        float p = 0.f;
        for (int c = tid; c < A_; c += 256) p += wt[c] * bh[c];
        red[tid] = p;
        __syncthreads();
        for (int step = 128; step > 0; step >>= 1) {
            if (tid < step) red[tid] += red[tid + step];
            __syncthreads();
        }
        if (tid == 0) g_c0[0] = red[0] + bt[0];
    }
}

// ---------------------------------------------------------------------------
// tf32 helpers
// ---------------------------------------------------------------------------
__device__ __forceinline__ unsigned f2tf32(float x) {
    unsigned r;
    asm("cvt.rna.tf32.f32 %0, %1;" : "=r"(r) : "f"(x));
    return r;
}
__device__ __forceinline__ void mma_tf32(float c[4], const unsigned a[4], const unsigned b[2]) {
    asm volatile(
        "mma.sync.aligned.m16n8k8.row.col.f32.tf32.tf32.f32 "
        "{%0,%1,%2,%3}, {%4,%5,%6,%7}, {%8,%9}, {%0,%1,%2,%3};"
        : "+f"(c[0]), "+f"(c[1]), "+f"(c[2]), "+f"(c[3])
        : "r"(a[0]), "r"(a[1]), "r"(a[2]), "r"(a[3]), "r"(b[0]), "r"(b[1]));
}

// ---------------------------------------------------------------------------
// NT GEMM (tf32 tensor cores): C[m,n] = sum_k A[m,k]*Bm[n,k]
// Block 64x64, BK=32, 128 threads (4 warps, 2x2), each warp 32x32
// = 2 m-tiles x 4 n-tiles of m16n8k8. Smem stride 36 -> conflict-free frags.
// ---------------------------------------------------------------------------
#define TBM 64
#define TBN 64
#define TBK 32
#define SSTR 36

__global__ void __launch_bounds__(128)
gemm_tf32_kernel(const float* __restrict__ A, const float* __restrict__ Bm,
                 int M, int N, int K, int which) {
    __shared__ __align__(16) float As[TBM][SSTR];
    __shared__ __align__(16) float Bs[TBN][SSTR];
    float* C = (which == 0) ? g_p1 : g_p2;

    int tid  = threadIdx.x;
    int warp = tid >> 5;
    int lane = tid & 31;
    int g    = lane >> 2;          // 0..7
    int tig  = lane & 3;           // 0..3
    int wm   = (warp & 1) * 32;    // warp row offset in tile
    int wn   = (warp >> 1) * 32;   // warp col offset in tile
    int m0   = blockIdx.y * TBM;
    int n0   = blockIdx.x * TBN;

    // global-load assignment: row = tid>>1 (0..63), half = tid&1 (16 floats)
    int lrow = tid >> 1;
    int lcol = (tid & 1) * 16;

    float acc[2][4][4] = {};
    float4 pa[4], pb[4];

    // prefetch first K-chunk
    {
        int am = m0 + lrow;
        #pragma unroll
        for (int j = 0; j < 4; j++) {
            int k = lcol + 4 * j;
            pa[j] = (am < M && k < K) ? *reinterpret_cast<const float4*>(A + (size_t)am * K + k)
                                      : make_float4(0.f, 0.f, 0.f, 0.f);
            pb[j] = (k < K) ? *reinterpret_cast<const float4*>(Bm + (size_t)(n0 + lrow) * K + k)
                            : make_float4(0.f, 0.f, 0.f, 0.f);
        }
    }

    for (int k0 = 0; k0 < K; k0 += TBK) {
        // commit prefetch to smem
        #pragma unroll
        for (int j = 0; j < 4; j++) {
            *reinterpret_cast<float4*>(&As[lrow][lcol + 4 * j]) = pa[j];
            *reinterpret_cast<float4*>(&Bs[lrow][lcol + 4 * j]) = pb[j];
        }
        __syncthreads();

        // prefetch next chunk
        int k1 = k0 + TBK;
        if (k1 < K) {
            int am = m0 + lrow;
            #pragma unroll
            for (int j = 0; j < 4; j++) {
                int k = k1 + lcol + 4 * j;
                pa[j] = (am < M && k < K) ? *reinterpret_cast<const float4*>(A + (size_t)am * K + k)
                                          : make_float4(0.f, 0.f, 0.f, 0.f);
                pb[j] = (k < K) ? *reinterpret_cast<const float4*>(Bm + (size_t)(n0 + lrow) * K + k)
                                : make_float4(0.f, 0.f, 0.f, 0.f);
            }
        }

        // compute: 4 k-steps of 8
        #pragma unroll
        for (int kk = 0; kk < TBK; kk += 8) {
            unsigned af[2][4], bf[4][2];
            #pragma unroll
            for (int mt = 0; mt < 2; mt++) {
                int m = wm + mt * 16;
                af[mt][0] = f2tf32(As[m + g][kk + tig]);
                af[mt][1] = f2tf32(As[m + g + 8][kk + tig]);
                af[mt][2] = f2tf32(As[m + g][kk + tig + 4]);
                af[mt][3] = f2tf32(As[m + g + 8][kk + tig + 4]);
            }
            #pragma unroll
            for (int nt = 0; nt < 4; nt++) {
                int n = wn + nt * 8;
                bf[nt][0] = f2tf32(Bs[n + g][kk + tig]);
                bf[nt][1] = f2tf32(Bs[n + g][kk + tig + 4]);
            }
            #pragma unroll
            for (int mt = 0; mt < 2; mt++)
                #pragma unroll
                for (int nt = 0; nt < 4; nt++)
                    mma_tf32(acc[mt][nt], af[mt], bf[nt]);
        }
        __syncthreads();
    }

    // write C
    #pragma unroll
    for (int mt = 0; mt < 2; mt++) {
        int mr0 = m0 + wm + mt * 16 + g;
        int mr1 = mr0 + 8;
        #pragma unroll
        for (int nt = 0; nt < 4; nt++) {
            int nc = n0 + wn + nt * 8 + 2 * tig;
            if (mr0 < M)
                *reinterpret_cast<float2*>(C + (size_t)mr0 * N + nc) =
                    make_float2(acc[mt][nt][0], acc[mt][nt][1]);
            if (mr1 < M)
                *reinterpret_cast<float2*>(C + (size_t)mr1 * N + nc) =
                    make_float2(acc[mt][nt][2], acc[mt][nt][3]);
        }
    }
}

// ---------------------------------------------------------------------------
// final: alpha[b,l,p] = c0 + sum_a v[a]*tanh(p1[b,p,a]*p2[b,l,a])
// tanh(x) = 1 - 2/(exp(2x)+1) via ex2.approx + rcp.approx (abs err ~1e-6)
// ---------------------------------------------------------------------------
#define AC 64
__global__ void __launch_bounds__(256) final_kernel(float* __restrict__ out) {
    __shared__ float p1s[32][AC + 1];
    __shared__ float p2s[16][AC + 1];
    __shared__ float vs[AC];
    int tid = threadIdx.x;
    int tx = tid & 15, ty = tid >> 4;
    int b = blockIdx.z;
    int l0 = blockIdx.y * 16;
    int pp0 = blockIdx.x * 32;
    const float* p1b = g_p1 + ((size_t)b * P_ + pp0) * A_;
    const float* p2b = g_p2 + ((size_t)b * L_ + l0) * A_;
    float acc0 = 0.f, acc1 = 0.f;
    const float TWO_LOG2E = 2.8853900817779268f;   // 2*log2(e)

    for (int a0 = 0; a0 < A_; a0 += AC) {
        #pragma unroll
        for (int i = 0; i < 2; i++) {
            int idx = tid + i * 256;
            int r = idx >> 4, c4 = (idx & 15) << 2;
            float4 v4 = make_float4(0.f, 0.f, 0.f, 0.f);
            if (pp0 + r < P_)
                v4 = *reinterpret_cast<const float4*>(p1b + (size_t)r * A_ + a0 + c4);
            p1s[r][c4 + 0] = v4.x; p1s[r][c4 + 1] = v4.y;
            p1s[r][c4 + 2] = v4.z; p1s[r][c4 + 3] = v4.w;
        }
        {
            int r = tid >> 4, c4 = (tid & 15) << 2;
            float4 v4 = *reinterpret_cast<const float4*>(p2b + (size_t)r * A_ + a0 + c4);
            p2s[r][c4 + 0] = v4.x; p2s[r][c4 + 1] = v4.y;
            p2s[r][c4 + 2] = v4.z; p2s[r][c4 + 3] = v4.w;
        }
        if (tid < 16) {
            float4 v4 = *reinterpret_cast<const float4*>(g_v + a0 + (tid << 2));
            vs[(tid << 2) + 0] = v4.x; vs[(tid << 2) + 1] = v4.y;
            vs[(tid << 2) + 2] = v4.z; vs[(tid << 2) + 3] = v4.w;
        }
        __syncthreads();
        #pragma unroll 8
        for (int a = 0; a < AC; a++) {
            float w  = vs[a];
            float q2 = p2s[ty][a] * TWO_LOG2E;         // fold 2*log2(e) into p2
            float x0 = p1s[2 * tx][a] * q2;
            float x1 = p1s[2 * tx + 1][a] * q2;
            float e0, e1, r0, r1;
            asm("ex2.approx.f32 %0, %1;" : "=f"(e0) : "f"(x0));
            asm("ex2.approx.f32 %0, %1;" : "=f"(e1) : "f"(x1));
            asm("rcp.approx.f32 %0, %1;" : "=f"(r0) : "f"(e0 + 1.f));
            asm("rcp.approx.f32 %0, %1;" : "=f"(r1) : "f"(e1 + 1.f));
            float t0 = fmaf(-2.f, r0, 1.f);            // tanh(x0)
            float t1 = fmaf(-2.f, r1, 1.f);            // tanh(x1)
            acc0 = fmaf(w, t0, acc0);
            acc1 = fmaf(w, t1, acc1);
        }
        __syncthreads();
    }
    float c0 = g_c0[0];
    int l = l0 + ty;
    int p = pp0 + 2 * tx;
    float* ob = out + ((size_t)b * L_ + l) * P_;
    if (p < P_)     ob[p]     = acc0 + c0;
    if (p + 1 < P_) ob[p + 1] = acc1 + c0;
}

// ---------------------------------------------------------------------------
extern "C" void kernel_launch(void* const* d_in, const int* in_sizes, int n_in,
                              void* d_out, int out_size) {
    (void)in_sizes; (void)n_in; (void)out_size;
    const float* x1 = (const float*)d_in[0];
    const float* x2 = (const float*)d_in[1];
    const float* W1 = (const float*)d_in[2];
    const float* W2 = (const float*)d_in[3];
    const float* Wh = (const float*)d_in[4];
    const float* bh = (const float*)d_in[5];
    const float* wt = (const float*)d_in[6];
    const float* bt = (const float*)d_in[7];
    float* out = (float*)d_out;

    prep_v_kernel<<<32, 256>>>(Wh, wt, bh, bt);
    gemm_tf32_kernel<<<dim3(A_ / TBN, (B_ * P_ + TBM - 1) / TBM), 128>>>(x1, W1, B_ * P_, A_, D1_, 0);
    gemm_tf32_kernel<<<dim3(A_ / TBN, (B_ * L_ + TBM - 1) / TBM), 128>>>(x2, W2, B_ * L_, A_, D2_, 1);
    final_kernel<<<dim3((P_ + 31) / 32, L_ / 16, B_), 256>>>(out);
}

// round 3
// speedup vs baseline: 1.1927x; 1.1927x over previous
#include <cuda_runtime.h>
#include <cstdint>

#define B_  8
#define P_  196
#define L_  80
#define D1_ 2048
#define D2_ 300
#define A_  1024

// Scratch (device globals: allocation-free contract)
__device__ float g_p1[(size_t)B_ * P_ * A_];   // 1568 x 1024
__device__ float g_p2[(size_t)B_ * L_ * A_];   // 640 x 1024
__device__ float g_v[A_];
__device__ float g_c0[1];

// ---------------------------------------------------------------------------
// prep: v[a] = sum_c wt[c]*Wh[c][a];  c0 = wt.bh + bt
// ---------------------------------------------------------------------------
__global__ void prep_v_kernel(const float* __restrict__ Wh, const float* __restrict__ wt,
                              const float* __restrict__ bh, const float* __restrict__ bt) {
    __shared__ float red[256];
    int tid = threadIdx.x;
    int a_local = tid & 31;
    int cg = tid >> 5;                       // 0..7
    int a = blockIdx.x * 32 + a_local;
    float s = 0.f;
    int cbeg = cg * 128;
    #pragma unroll 8
    for (int c = cbeg; c < cbeg + 128; c++)
        s += wt[c] * Wh[(size_t)c * A_ + a];
    red[tid] = s;
    __syncthreads();
    if (cg == 0) {
        float t = 0.f;
        #pragma unroll
        for (int g = 0; g < 8; g++) t += red[g * 32 + a_local];
        g_v[a] = t;
    }
    __syncthreads();
    if (blockIdx.x == 0) {
        float p = 0.f;
        for (int c = tid; c < A_; c += 256) p += wt[c] * bh[c];
        red[tid] = p;
        __syncthreads();
        for (int step = 128; step > 0; step >>= 1) {
            if (tid < step) red[tid] += red[tid + step];
            __syncthreads();
        }
        if (tid == 0) g_c0[0] = red[0] + bt[0];
    }
}

// ---------------------------------------------------------------------------
// tf32 helpers
// ---------------------------------------------------------------------------
__device__ __forceinline__ unsigned f2tf32(float x) {
    unsigned r;
    asm("cvt.rna.tf32.f32 %0, %1;" : "=r"(r) : "f"(x));
    return r;
}
__device__ __forceinline__ void mma_tf32(float c[4], const unsigned a[4], const unsigned b[2]) {
    asm volatile(
        "mma.sync.aligned.m16n8k8.row.col.f32.tf32.tf32.f32 "
        "{%0,%1,%2,%3}, {%4,%5,%6,%7}, {%8,%9}, {%0,%1,%2,%3};"
        : "+f"(c[0]), "+f"(c[1]), "+f"(c[2]), "+f"(c[3])
        : "r"(a[0]), "r"(a[1]), "r"(a[2]), "r"(a[3]), "r"(b[0]), "r"(b[1]));
}

// ---------------------------------------------------------------------------
// NT GEMM (tf32 tensor cores): C[m,n] = sum_k A[m,k]*Bm[n,k]
// Block 64x64, BK=32, 128 threads (4 warps, 2x2), each warp 32x32.
// Smem holds PRE-CONVERTED tf32 bits -> inner loop is pure LDS + HMMA.
// Stride 36 -> fragment LDS provably conflict-free (bank = 4*g+tig = lane).
// ---------------------------------------------------------------------------
#define TBM 64
#define TBN 64
#define TBK 32
#define SSTR 36

__global__ void __launch_bounds__(128)
gemm_tf32_kernel(const float* __restrict__ A, const float* __restrict__ Bm,
                 int M, int N, int K, int which) {
    __shared__ __align__(16) unsigned As[TBM][SSTR];
    __shared__ __align__(16) unsigned Bs[TBN][SSTR];
    float* C = (which == 0) ? g_p1 : g_p2;

    int tid  = threadIdx.x;
    int warp = tid >> 5;
    int lane = tid & 31;
    int g    = lane >> 2;          // 0..7
    int tig  = lane & 3;           // 0..3
    int wm   = (warp & 1) * 32;    // warp row offset in tile
    int wn   = (warp >> 1) * 32;   // warp col offset in tile
    int m0   = blockIdx.y * TBM;
    int n0   = blockIdx.x * TBN;

    // global-load assignment: row = tid>>1 (0..63), half = tid&1 (16 floats)
    int lrow = tid >> 1;
    int lcol = (tid & 1) * 16;

    float acc[2][4][4] = {};
    float4 pa[4], pb[4];

    // prefetch first K-chunk
    {
        int am = m0 + lrow;
        #pragma unroll
        for (int j = 0; j < 4; j++) {
            int k = lcol + 4 * j;
            pa[j] = (am < M && k < K) ? *reinterpret_cast<const float4*>(A + (size_t)am * K + k)
                                      : make_float4(0.f, 0.f, 0.f, 0.f);
            pb[j] = (k < K) ? *reinterpret_cast<const float4*>(Bm + (size_t)(n0 + lrow) * K + k)
                            : make_float4(0.f, 0.f, 0.f, 0.f);
        }
    }

    for (int k0 = 0; k0 < K; k0 += TBK) {
        // commit prefetch to smem, converting to tf32 bits at store time
        #pragma unroll
        for (int j = 0; j < 4; j++) {
            uint4 ua = make_uint4(f2tf32(pa[j].x), f2tf32(pa[j].y), f2tf32(pa[j].z), f2tf32(pa[j].w));
            uint4 ub = make_uint4(f2tf32(pb[j].x), f2tf32(pb[j].y), f2tf32(pb[j].z), f2tf32(pb[j].w));
            *reinterpret_cast<uint4*>(&As[lrow][lcol + 4 * j]) = ua;
            *reinterpret_cast<uint4*>(&Bs[lrow][lcol + 4 * j]) = ub;
        }
        __syncthreads();

        // prefetch next chunk
        int k1 = k0 + TBK;
        if (k1 < K) {
            int am = m0 + lrow;
            #pragma unroll
            for (int j = 0; j < 4; j++) {
                int k = k1 + lcol + 4 * j;
                pa[j] = (am < M && k < K) ? *reinterpret_cast<const float4*>(A + (size_t)am * K + k)
                                          : make_float4(0.f, 0.f, 0.f, 0.f);
                pb[j] = (k < K) ? *reinterpret_cast<const float4*>(Bm + (size_t)(n0 + lrow) * K + k)
                                : make_float4(0.f, 0.f, 0.f, 0.f);
            }
        }

        // compute: 4 k-steps of 8 — pure LDS + HMMA
        #pragma unroll
        for (int kk = 0; kk < TBK; kk += 8) {
            unsigned af[2][4], bf[4][2];
            #pragma unroll
            for (int mt = 0; mt < 2; mt++) {
                int m = wm + mt * 16;
                af[mt][0] = As[m + g][kk + tig];
                af[mt][1] = As[m + g + 8][kk + tig];
                af[mt][2] = As[m + g][kk + tig + 4];
                af[mt][3] = As[m + g + 8][kk + tig + 4];
            }
            #pragma unroll
            for (int nt = 0; nt < 4; nt++) {
                int n = wn + nt * 8;
                bf[nt][0] = Bs[n + g][kk + tig];
                bf[nt][1] = Bs[n + g][kk + tig + 4];
            }
            #pragma unroll
            for (int mt = 0; mt < 2; mt++)
                #pragma unroll
                for (int nt = 0; nt < 4; nt++)
                    mma_tf32(acc[mt][nt], af[mt], bf[nt]);
        }
        __syncthreads();
    }

    // write C
    #pragma unroll
    for (int mt = 0; mt < 2; mt++) {
        int mr0 = m0 + wm + mt * 16 + g;
        int mr1 = mr0 + 8;
        #pragma unroll
        for (int nt = 0; nt < 4; nt++) {
            int nc = n0 + wn + nt * 8 + 2 * tig;
            if (mr0 < M)
                *reinterpret_cast<float2*>(C + (size_t)mr0 * N + nc) =
                    make_float2(acc[mt][nt][0], acc[mt][nt][1]);
            if (mr1 < M)
                *reinterpret_cast<float2*>(C + (size_t)mr1 * N + nc) =
                    make_float2(acc[mt][nt][2], acc[mt][nt][3]);
        }
    }
}

// ---------------------------------------------------------------------------
// final: alpha[b,l,p] = c0 + sum_a v[a]*tanh(p1[b,p,a]*p2[b,l,a])
// tanh via single MUFU.TANH (tanh.approx.f32). Per 2 elems: 4 LDS + 2 MUL
// + 2 MUFU + 2 FMA -> MUFU floor ~27us.
// ---------------------------------------------------------------------------
#define AC 64
__global__ void __launch_bounds__(256) final_kernel(float* __restrict__ out) {
    __shared__ float p1s[32][AC + 1];
    __shared__ float p2s[16][AC + 1];
    __shared__ float vs[AC];
    int tid = threadIdx.x;
    int tx = tid & 15, ty = tid >> 4;
    int b = blockIdx.z;
    int l0 = blockIdx.y * 16;
    int pp0 = blockIdx.x * 32;
    const float* p1b = g_p1 + ((size_t)b * P_ + pp0) * A_;
    const float* p2b = g_p2 + ((size_t)b * L_ + l0) * A_;
    float acc0 = 0.f, acc1 = 0.f;

    for (int a0 = 0; a0 < A_; a0 += AC) {
        #pragma unroll
        for (int i = 0; i < 2; i++) {
            int idx = tid + i * 256;
            int r = idx >> 4, c4 = (idx & 15) << 2;
            float4 v4 = make_float4(0.f, 0.f, 0.f, 0.f);
            if (pp0 + r < P_)
                v4 = *reinterpret_cast<const float4*>(p1b + (size_t)r * A_ + a0 + c4);
            p1s[r][c4 + 0] = v4.x; p1s[r][c4 + 1] = v4.y;
            p1s[r][c4 + 2] = v4.z; p1s[r][c4 + 3] = v4.w;
        }
        {
            int r = tid >> 4, c4 = (tid & 15) << 2;
            float4 v4 = *reinterpret_cast<const float4*>(p2b + (size_t)r * A_ + a0 + c4);
            p2s[r][c4 + 0] = v4.x; p2s[r][c4 + 1] = v4.y;
            p2s[r][c4 + 2] = v4.z; p2s[r][c4 + 3] = v4.w;
        }
        if (tid < 16) {
            float4 v4 = *reinterpret_cast<const float4*>(g_v + a0 + (tid << 2));
            vs[(tid << 2) + 0] = v4.x; vs[(tid << 2) + 1] = v4.y;
            vs[(tid << 2) + 2] = v4.z; vs[(tid << 2) + 3] = v4.w;
        }
        __syncthreads();
        #pragma unroll 8
        for (int a = 0; a < AC; a++) {
            float w  = vs[a];
            float y  = p2s[ty][a];
            float x0 = p1s[2 * tx][a] * y;
            float x1 = p1s[2 * tx + 1][a] * y;
            float t0, t1;
            asm("tanh.approx.f32 %0, %1;" : "=f"(t0) : "f"(x0));
            asm("tanh.approx.f32 %0, %1;" : "=f"(t1) : "f"(x1));
            acc0 = fmaf(w, t0, acc0);
            acc1 = fmaf(w, t1, acc1);
        }
        __syncthreads();
    }
    float c0 = g_c0[0];
    int l = l0 + ty;
    int p = pp0 + 2 * tx;
    float* ob = out + ((size_t)b * L_ + l) * P_;
    if (p < P_)     ob[p]     = acc0 + c0;
    if (p + 1 < P_) ob[p + 1] = acc1 + c0;
}

// ---------------------------------------------------------------------------
extern "C" void kernel_launch(void* const* d_in, const int* in_sizes, int n_in,
                              void* d_out, int out_size) {
    (void)in_sizes; (void)n_in; (void)out_size;
    const float* x1 = (const float*)d_in[0];
    const float* x2 = (const float*)d_in[1];
    const float* W1 = (const float*)d_in[2];
    const float* W2 = (const float*)d_in[3];
    const float* Wh = (const float*)d_in[4];
    const float* bh = (const float*)d_in[5];
    const float* wt = (const float*)d_in[6];
    const float* bt = (const float*)d_in[7];
    float* out = (float*)d_out;

    prep_v_kernel<<<32, 256>>>(Wh, wt, bh, bt);
    gemm_tf32_kernel<<<dim3(A_ / TBN, (B_ * P_ + TBM - 1) / TBM), 128>>>(x1, W1, B_ * P_, A_, D1_, 0);
    gemm_tf32_kernel<<<dim3(A_ / TBN, (B_ * L_ + TBM - 1) / TBM), 128>>>(x2, W2, B_ * L_, A_, D2_, 1);
    final_kernel<<<dim3((P_ + 31) / 32, L_ / 16, B_), 256>>>(out);
}

// round 13
// speedup vs baseline: 1.3526x; 1.1341x over previous
#include <cuda_runtime.h>
#include <cstdint>

#define B_  8
#define P_  196
#define L_  80
#define D1_ 2048
#define D2_ 300
#define A_  1024

// Scratch (device globals: allocation-free contract)
__device__ float g_p1[(size_t)B_ * P_ * A_];   // 1568 x 1024
__device__ float g_p2[(size_t)B_ * L_ * A_];   // 640 x 1024
__device__ float g_v[A_];
__device__ float g_c0[1];

// ---------------------------------------------------------------------------
// tf32 helpers
// ---------------------------------------------------------------------------
__device__ __forceinline__ unsigned f2tf32(float x) {
    unsigned r;
    asm("cvt.rna.tf32.f32 %0, %1;" : "=r"(r) : "f"(x));
    return r;
}
__device__ __forceinline__ void mma_tf32(float c[4], const unsigned a[4], const unsigned b[2]) {
    asm volatile(
        "mma.sync.aligned.m16n8k8.row.col.f32.tf32.tf32.f32 "
        "{%0,%1,%2,%3}, {%4,%5,%6,%7}, {%8,%9}, {%0,%1,%2,%3};"
        : "+f"(c[0]), "+f"(c[1]), "+f"(c[2]), "+f"(c[3])
        : "r"(a[0]), "r"(a[1]), "r"(a[2]), "r"(a[3]), "r"(b[0]), "r"(b[1]));
}

// ---------------------------------------------------------------------------
// GEMM geometry: NT, C[m,n] = sum_k A[m,k]*Bm[n,k]
// 64x64 block, BK=32, 128 threads (4 warps 2x2, warp tile 32x32).
// Double-buffered smem + double-buffered fragments, one sync per k-chunk.
// Smem stride 36 -> frag LDS conflict-free (bank = 4g+tig = lane).
// ---------------------------------------------------------------------------
#define TBM 64
#define TBN 64
#define TBK 32
#define SSTR 36

#define G1_NX (A_ / TBN)                         // 16
#define G1_NY ((B_ * P_ + TBM - 1) / TBM)        // 25
#define G1_BLOCKS (G1_NX * G1_NY)                // 400
#define G2_NX (A_ / TBN)                         // 16
#define G2_NY ((B_ * L_ + TBM - 1) / TBM)        // 10
#define G2_BLOCKS (G2_NX * G2_NY)                // 160
#define PREP_BLOCKS 32
#define FUSED_BLOCKS (G1_BLOCKS + G2_BLOCKS + PREP_BLOCKS)   // 592

struct Frag { unsigned af[2][4]; unsigned bf[4][2]; };

__device__ __forceinline__ void ldfrag(const unsigned (*As)[SSTR], const unsigned (*Bs)[SSTR],
                                       int wm, int wn, int g, int tig, int kk, Frag& f) {
    #pragma unroll
    for (int mt = 0; mt < 2; mt++) {
        int m = wm + mt * 16;
        f.af[mt][0] = As[m + g][kk + tig];
        f.af[mt][1] = As[m + g + 8][kk + tig];
        f.af[mt][2] = As[m + g][kk + tig + 4];
        f.af[mt][3] = As[m + g + 8][kk + tig + 4];
    }
    #pragma unroll
    for (int nt = 0; nt < 4; nt++) {
        int n = wn + nt * 8;
        f.bf[nt][0] = Bs[n + g][kk + tig];
        f.bf[nt][1] = Bs[n + g][kk + tig + 4];
    }
}

__device__ __forceinline__ void do_mma(float acc[2][4][4], const Frag& f) {
    #pragma unroll
    for (int mt = 0; mt < 2; mt++)
        #pragma unroll
        for (int nt = 0; nt < 4; nt++)
            mma_tf32(acc[mt][nt], f.af[mt], f.bf[nt]);
}

struct SmemGemm {
    unsigned As[2][TBM][SSTR];
    unsigned Bs[2][TBN][SSTR];
};

__device__ __forceinline__ void gemm_body(SmemGemm& sm,
                                          const float* __restrict__ A,
                                          const float* __restrict__ Bm,
                                          float* __restrict__ C,
                                          int M, int N, int K, int bx, int by) {
    int tid  = threadIdx.x;
    int warp = tid >> 5;
    int lane = tid & 31;
    int g    = lane >> 2;
    int tig  = lane & 3;
    int wm   = (warp & 1) * 32;
    int wn   = (warp >> 1) * 32;
    int m0   = by * TBM;
    int n0   = bx * TBN;

    int lrow = tid >> 1;           // 0..63
    int lcol = (tid & 1) * 16;     // 0 or 16

    float acc[2][4][4] = {};
    float4 pa[4], pb[4];
    int am = m0 + lrow;
    const float* Arow = A + (size_t)am * K;
    const float* Brow = Bm + (size_t)(n0 + lrow) * K;
    bool aok = (am < M);

    // ---- load chunk 0 ----
    #pragma unroll
    for (int j = 0; j < 4; j++) {
        int k = lcol + 4 * j;
        pa[j] = (aok && k < K) ? *reinterpret_cast<const float4*>(Arow + k)
                               : make_float4(0.f, 0.f, 0.f, 0.f);
        pb[j] = (k < K) ? *reinterpret_cast<const float4*>(Brow + k)
                        : make_float4(0.f, 0.f, 0.f, 0.f);
    }
    #pragma unroll
    for (int j = 0; j < 4; j++) {
        uint4 ua = make_uint4(f2tf32(pa[j].x), f2tf32(pa[j].y), f2tf32(pa[j].z), f2tf32(pa[j].w));
        uint4 ub = make_uint4(f2tf32(pb[j].x), f2tf32(pb[j].y), f2tf32(pb[j].z), f2tf32(pb[j].w));
        *reinterpret_cast<uint4*>(&sm.As[0][lrow][lcol + 4 * j]) = ua;
        *reinterpret_cast<uint4*>(&sm.Bs[0][lrow][lcol + 4 * j]) = ub;
    }
    __syncthreads();

    Frag f0, f1;
    ldfrag(sm.As[0], sm.Bs[0], wm, wn, g, tig, 0, f0);

    int nIter = (K + TBK - 1) / TBK;
    for (int it = 0; it < nIter; it++) {
        int buf = it & 1;
        bool has_next = (it + 1 < nIter);

        if (has_next) {
            int kbase = (it + 1) * TBK;
            #pragma unroll
            for (int j = 0; j < 4; j++) {
                int k = kbase + lcol + 4 * j;
                pa[j] = (aok && k < K) ? *reinterpret_cast<const float4*>(Arow + k)
                                       : make_float4(0.f, 0.f, 0.f, 0.f);
                pb[j] = (k < K) ? *reinterpret_cast<const float4*>(Brow + k)
                                : make_float4(0.f, 0.f, 0.f, 0.f);
            }
        }

        ldfrag(sm.As[buf], sm.Bs[buf], wm, wn, g, tig, 8, f1);
        do_mma(acc, f0);                                  // kk = 0
        ldfrag(sm.As[buf], sm.Bs[buf], wm, wn, g, tig, 16, f0);
        do_mma(acc, f1);                                  // kk = 8
        ldfrag(sm.As[buf], sm.Bs[buf], wm, wn, g, tig, 24, f1);
        do_mma(acc, f0);                                  // kk = 16

        if (has_next) {
            int nb = buf ^ 1;
            #pragma unroll
            for (int j = 0; j < 4; j++) {
                uint4 ua = make_uint4(f2tf32(pa[j].x), f2tf32(pa[j].y), f2tf32(pa[j].z), f2tf32(pa[j].w));
                uint4 ub = make_uint4(f2tf32(pb[j].x), f2tf32(pb[j].y), f2tf32(pb[j].z), f2tf32(pb[j].w));
                *reinterpret_cast<uint4*>(&sm.As[nb][lrow][lcol + 4 * j]) = ua;
                *reinterpret_cast<uint4*>(&sm.Bs[nb][lrow][lcol + 4 * j]) = ub;
            }
        }
        __syncthreads();
        if (has_next)
            ldfrag(sm.As[buf ^ 1], sm.Bs[buf ^ 1], wm, wn, g, tig, 0, f0);
        do_mma(acc, f1);                                  // kk = 24
    }

    // write C
    #pragma unroll
    for (int mt = 0; mt < 2; mt++) {
        int mr0 = m0 + wm + mt * 16 + g;
        int mr1 = mr0 + 8;
        #pragma unroll
        for (int nt = 0; nt < 4; nt++) {
            int nc = n0 + wn + nt * 8 + 2 * tig;
            if (mr0 < M)
                *reinterpret_cast<float2*>(C + (size_t)mr0 * N + nc) =
                    make_float2(acc[mt][nt][0], acc[mt][nt][1]);
            if (mr1 < M)
                *reinterpret_cast<float2*>(C + (size_t)mr1 * N + nc) =
                    make_float2(acc[mt][nt][2], acc[mt][nt][3]);
        }
    }
}

// prep (128 threads): block pb in [0,32): v[a] for 32 a's; block 0 also does c0.
__device__ __forceinline__ void prep_body(const float* __restrict__ Wh,
                                          const float* __restrict__ wt,
                                          const float* __restrict__ bh,
                                          const float* __restrict__ bt, int pb) {
    __shared__ float red[128];
    int tid = threadIdx.x;
    int a_local = tid & 31;
    int cg = tid >> 5;                       // 0..3
    int a = pb * 32 + a_local;
    float s = 0.f;
    int cbeg = cg * 256;
    #pragma unroll 8
    for (int c = cbeg; c < cbeg + 256; c++)
        s += wt[c] * Wh[(size_t)c * A_ + a];
    red[tid] = s;
    __syncthreads();
    if (cg == 0) {
        float t = red[a_local] + red[32 + a_local] + red[64 + a_local] + red[96 + a_local];
        g_v[a] = t;
    }
    __syncthreads();
    if (pb == 0) {
        float p = 0.f;
        for (int c = tid; c < A_; c += 128) p += wt[c] * bh[c];
        red[tid] = p;
        __syncthreads();
        for (int step = 64; step > 0; step >>= 1) {
            if (tid < step) red[tid] += red[tid + step];
            __syncthreads();
        }
        if (tid == 0) g_c0[0] = red[0] + bt[0];
    }
}

// ---------------------------------------------------------------------------
// Fused front kernel: [0,400) GEMM1 tiles, [400,560) GEMM2 tiles, [560,592) prep
// ---------------------------------------------------------------------------
__global__ void __launch_bounds__(128)
fused_front_kernel(const float* __restrict__ x1, const float* __restrict__ x2,
                   const float* __restrict__ W1, const float* __restrict__ W2,
                   const float* __restrict__ Wh, const float* __restrict__ wt,
                   const float* __restrict__ bh, const float* __restrict__ bt) {
    __shared__ SmemGemm sm;
    int blk = blockIdx.x;
    if (blk < G1_BLOCKS) {
        gemm_body(sm, x1, W1, g_p1, B_ * P_, A_, D1_, blk % G1_NX, blk / G1_NX);
    } else if (blk < G1_BLOCKS + G2_BLOCKS) {
        int r = blk - G1_BLOCKS;
        gemm_body(sm, x2, W2, g_p2, B_ * L_, A_, D2_, r % G2_NX, r / G2_NX);
    } else {
        prep_body(Wh, wt, bh, bt, blk - G1_BLOCKS - G2_BLOCKS);
    }
}

// ---------------------------------------------------------------------------
// final: alpha[b,l,p] = c0 + sum_a v[a]*tanh(p1[b,p,a]*p2[b,l,a])
// 512 threads, 1 elem/thread (32 P x 16 L tile): 16 warps/block to saturate
// the MUFU (tanh) pipe.
// ---------------------------------------------------------------------------
#define AC 64
__global__ void __launch_bounds__(512) final_kernel(float* __restrict__ out) {
    __shared__ float p1s[32][AC + 1];
    __shared__ float p2s[16][AC + 1];
    __shared__ float vs[AC];
    int tid = threadIdx.x;
    int tx = tid & 31;            // p within tile
    int ty = tid >> 5;            // l within tile (0..15)
    int b = blockIdx.z;
    int l0 = blockIdx.y * 16;
    int pp0 = blockIdx.x * 32;
    const float* p1b = g_p1 + ((size_t)b * P_ + pp0) * A_;
    const float* p2b = g_p2 + ((size_t)b * L_ + l0) * A_;
    float acc = 0.f;

    for (int a0 = 0; a0 < A_; a0 += AC) {
        // p1 tile 32x64: 512 float4, one per thread
        {
            int r = tid >> 4, c4 = (tid & 15) << 2;
            float4 v4 = make_float4(0.f, 0.f, 0.f, 0.f);
            if (pp0 + r < P_)
                v4 = *reinterpret_cast<const float4*>(p1b + (size_t)r * A_ + a0 + c4);
            p1s[r][c4 + 0] = v4.x; p1s[r][c4 + 1] = v4.y;
            p1s[r][c4 + 2] = v4.z; p1s[r][c4 + 3] = v4.w;
        }
        // p2 tile 16x64: 256 float4
        if (tid < 256) {
            int r = tid >> 4, c4 = (tid & 15) << 2;
            float4 v4 = *reinterpret_cast<const float4*>(p2b + (size_t)r * A_ + a0 + c4);
            p2s[r][c4 + 0] = v4.x; p2s[r][c4 + 1] = v4.y;
            p2s[r][c4 + 2] = v4.z; p2s[r][c4 + 3] = v4.w;
        }
        if (tid < 16) {
            float4 v4 = *reinterpret_cast<const float4*>(g_v + a0 + (tid << 2));
            vs[(tid << 2) + 0] = v4.x; vs[(tid << 2) + 1] = v4.y;
            vs[(tid << 2) + 2] = v4.z; vs[(tid << 2) + 3] = v4.w;
        }
        __syncthreads();
        #pragma unroll 16
        for (int a = 0; a < AC; a++) {
            float x = p1s[tx][a] * p2s[ty][a];
            float t;
            asm("tanh.approx.f32 %0, %1;" : "=f"(t) : "f"(x));
            acc = fmaf(vs[a], t, acc);
        }
        __syncthreads();
    }
    int l = l0 + ty;
    int p = pp0 + tx;
    if (p < P_)
        out[((size_t)b * L_ + l) * P_ + p] = acc + g_c0[0];
}

// ---------------------------------------------------------------------------
extern "C" void kernel_launch(void* const* d_in, const int* in_sizes, int n_in,
                              void* d_out, int out_size) {
    (void)in_sizes; (void)n_in; (void)out_size;
    const float* x1 = (const float*)d_in[0];
    const float* x2 = (const float*)d_in[1];
    const float* W1 = (const float*)d_in[2];
    const float* W2 = (const float*)d_in[3];
    const float* Wh = (const float*)d_in[4];
    const float* bh = (const float*)d_in[5];
    const float* wt = (const float*)d_in[6];
    const float* bt = (const float*)d_in[7];
    float* out = (float*)d_out;

    fused_front_kernel<<<FUSED_BLOCKS, 128>>>(x1, x2, W1, W2, Wh, wt, bh, bt);
    final_kernel<<<dim3((P_ + 31) / 32, L_ / 16, B_), 512>>>(out);
}